// round 17
// baseline (speedup 1.0000x reference)
#include <cuda_runtime.h>
#include <cuda_pipeline_primitives.h>

// PSRoIPool (R-FCN style), fp32.
// features: [B=4, C=490, H=38, W=38], rois: [R=256, 5], out: [R,10,7,7]
// c = (d*P + ph)*P + pw
//
// Numerics (locked, PASS @ rel_err 2.845666e-08):
//  - xs/ys/xe/ye exact (integer/16); bin = roi * RN(1/7) (XLA reciprocal-
//    multiply strength reduction, NOT fdiv)
//  - edges via fmaf; two-level ascending summation (rows of w, then h)
//
// Perf (R17): R12-R16 converged at ncu 6.7-6.9us under five different
// memory structures -> NOT memory bound. issue=36.8% x 12.8k cyc == ~700
// warp-instructions/warp: ISSUE BOUND, dominated by the staging loop's
// runtime div/mod and loop overhead. This round: fully unrolled staging
// (8 cp.async per thread, constant strides, no div/mod/loop), everything
// else unchanged. Target ~3x fewer instructions per thread.

#define P_ 7
#define D_ 10
#define H_ 38
#define W_ 38
#define C_ 490
#define R_ 256
#define B_ 4
#define PLANE_ (H_ * W_)          // 1444 floats, 5776 B
#define PLANE4_ (PLANE_ / 4)      // 361 float4
#define BSTRIDE4_ (C_ * PLANE4_)  // float4 stride between batches
#define SCALE_ 0.0625f

__global__ __launch_bounds__(256) void psroi_kernel(
    const float* __restrict__ feat,
    const float* __restrict__ rois,
    float* __restrict__ out)
{
    __shared__ float4 sf4[B_ * PLANE4_];         // 23104 B

    const int c   = blockIdx.x;                  // 0..489, channel plane
    const int tid = threadIdx.x;                 // 0..255 == ROI index

    // ---- staging: fully unrolled, zero div/mod/loop overhead ----
    // PLANE4_ = 361 = 256 + 105: each thread copies q=tid and (tid<105)
    // q=tid+256, for each of the 4 batch planes. 8 LDGSTS total.
    {
        const float4* s0 = (const float4*)feat + (size_t)c * PLANE4_ + tid;
        const bool tail = (tid < PLANE4_ - 256);
        #pragma unroll
        for (int b = 0; b < B_; ++b) {
            const float4* s = s0 + (size_t)b * BSTRIDE4_;
            float4*       d = &sf4[b * PLANE4_ + tid];
            __pipeline_memcpy_async(d, s, 16);
            if (tail)
                __pipeline_memcpy_async(d + 256, s + 256, 16);
        }
        __pipeline_commit();
    }

    // ---- window math in the copy shadow (locked numerics) ----
    const float* roi = rois + tid * 5;
    int b = (int)roi[0];

    int pw = c % P_;                // column bin (bin_w, xs)
    int ph = (c / P_) % P_;         // row bin    (bin_h, ys)

    // jnp.round == round-half-to-even == rintf (RN); *0.0625 exact
    float xs = __fmul_rn(rintf(roi[1]), SCALE_);
    float ys = __fmul_rn(rintf(roi[2]), SCALE_);
    float xe = __fmul_rn(rintf(__fadd_rn(roi[3], 1.0f)), SCALE_);
    float ye = __fmul_rn(rintf(__fadd_rn(roi[4], 1.0f)), SCALE_);

    const float RECIP7 = 1.0f / 7.0f;   // RN(1/7)
    float bin_w = __fmul_rn(fmaxf(__fadd_rn(xe, -xs), 0.1f), RECIP7);
    float bin_h = __fmul_rn(fmaxf(__fadd_rn(ye, -ys), 0.1f), RECIP7);

    // edges: single-rounding FMA; clip to [0,H]/[0,W]
    float hs = floorf(fmaf((float) ph,      bin_h, ys));
    float he = ceilf (fmaf((float)(ph + 1), bin_h, ys));
    float ws = floorf(fmaf((float) pw,      bin_w, xs));
    float we = ceilf (fmaf((float)(pw + 1), bin_w, xs));

    int hstart = (int)fminf(fmaxf(hs, 0.0f), (float)H_);
    int hend   = (int)fminf(fmaxf(he, 0.0f), (float)H_);
    int wstart = (int)fminf(fmaxf(ws, 0.0f), (float)W_);
    int wend   = (int)fminf(fmaxf(we, 0.0f), (float)W_);

    int hspan = hend - hstart;          // 0..4 (roi wh <= 256 -> span <= 4)
    int wspan = wend - wstart;          // 0..4

    __pipeline_wait_prior(0);
    __syncthreads();

    const float* base = (const float*)sf4 + b * PLANE_ + hstart * W_ + wstart;

    // predicated 4x4 gather from smem, exact two-level ascending reduce
    float v[4][4];
    #pragma unroll
    for (int i = 0; i < 4; ++i) {
        #pragma unroll
        for (int j = 0; j < 4; ++j) {
            bool valid = (i < hspan) && (j < wspan);
            v[i][j] = valid ? base[i * W_ + j] : 0.0f;
        }
    }

    float sum = 0.0f;
    #pragma unroll
    for (int i = 0; i < 4; ++i) {
        float rsum = 0.0f;
        #pragma unroll
        for (int j = 0; j < 4; ++j)
            rsum = __fadd_rn(rsum, v[i][j]);   // ascending w
        sum = __fadd_rn(sum, rsum);            // ascending h
    }

    int cnt = hspan * wspan;
    // out[r][d][ph][pw] = out[tid*490 + c]
    out[tid * C_ + c] = (cnt > 0) ? __fdiv_rn(sum, (float)cnt) : 0.0f;
}

extern "C" void kernel_launch(void* const* d_in, const int* in_sizes, int n_in,
                              void* d_out, int out_size)
{
    const float* feat = (const float*)d_in[0];
    const float* rois = (const float*)d_in[1];
    float* out = (float*)d_out;

    psroi_kernel<<<C_, 256>>>(feat, rois, out);   // 490 blocks, 1 ROI/thread
}